// round 15
// baseline (speedup 1.0000x reference)
#include <cuda_runtime.h>
#include <cuda_bf16.h>
#include <cstdint>

// Problem: x [32,64,64,64] NCHW fp32, emb0/1/2 [512,64] fp32, idx int
#define NPIX   131072
#define D      64
#define HW     4096
#define KMAX   1024
#define OUT_ELEMS 8388608
#define CTA_PIX 256
#define TPB    256
#define MARGIN_T 0.30f

// smem layout (bytes). B (32 KB) overlays dead A (32 KB staging region).
#define SM_A    0            // 256 rows x 128B (xh bf16, swizzled) = 32 KB
#define SM_B    0            // 256 rows x 128B (c bf16, swizzled) overlay
#define SM_SHN  32768        // 1024 f32 (-0.5||c||^2) = 4 KB
#define SMEM_TOTAL 36864
// phase-2 overlays (inside dead A/B region, after final chunk syncthreads)
#define SM_CS   0            // 256 x 12 f32 candidate scores (12 KB)
#define SM_CI   12288        // 256 x 12 i32 candidate indices (12 KB)
#define SM_RED  24576        // 256 f32

// Scratch (no cudaMalloc allowed)
__device__ int      g_hist[KMAX];
__device__ float    g_shn[KMAX];
__device__ float    g_lossacc;
// bf16 codes, swizzled per-256-row chunk: 4 chunks x 256 rows x 128B
__device__ __align__(16) unsigned char g_bsplit[KMAX * 128];

// ---------------------------------------------------------------------------
__device__ __forceinline__ uint32_t smem_u32(const void* p) {
    uint32_t a;
    asm("{ .reg .u64 t; cvta.to.shared.u64 t, %1; cvt.u32.u64 %0, t; }"
        : "=r"(a) : "l"(p));
    return a;
}

#define LDSM_X4(r0, r1, r2, r3, addr) \
    asm volatile("ldmatrix.sync.aligned.m8n8.x4.shared.b16 {%0,%1,%2,%3}, [%4];" \
        : "=r"(r0), "=r"(r1), "=r"(r2), "=r"(r3) : "r"(addr))

#define MMA(dd, a0, a1, a2, a3, b0, b1) \
    asm volatile("mma.sync.aligned.m16n8k16.row.col.f32.bf16.bf16.f32 " \
        "{%0,%1,%2,%3},{%4,%5,%6,%7},{%8,%9},{%0,%1,%2,%3};" \
        : "+f"((dd)[0]), "+f"((dd)[1]), "+f"((dd)[2]), "+f"((dd)[3]) \
        : "r"(a0), "r"(a1), "r"(a2), "r"(a3), "r"(b0), "r"(b1))

__device__ __forceinline__ const float* code_row(int k, const float* e0,
                                                 const float* e1, const float* e2,
                                                 int idxv) {
    if (k < 512) return e0 + (size_t)k * D;
    const float* e = (idxv == 1) ? e1 : e2;
    return e + (size_t)(k - 512) * D;
}

// ---------------------------------------------------------------------------
// Kernel 0: zero hist/loss + fp32 (-0.5*||c||^2) per code (one warp per code)
// ---------------------------------------------------------------------------
__global__ void prep_norms(const float* __restrict__ e0, const float* __restrict__ e1,
                           const float* __restrict__ e2, const int* __restrict__ idxp) {
    int idxv = *idxp;
    int K = (idxv == 0) ? 512 : 1024;
    int lane = threadIdx.x & 31;
    int k = blockIdx.x * 4 + (threadIdx.x >> 5);
    float s = 0.f;
    if (k < K) {
        const float* c = code_row(k, e0, e1, e2, idxv);
        float a = c[lane], b = c[lane + 32];
        s = a * a + b * b;
    }
    #pragma unroll
    for (int off = 16; off > 0; off >>= 1) s += __shfl_xor_sync(0xffffffffu, s, off);
    if (lane == 0) {
        g_shn[k] = -0.5f * s;
        g_hist[k] = 0;
        if (k == 0) g_lossacc = 0.f;
    }
}

// ---------------------------------------------------------------------------
// Kernel 1: codes -> bf16, swizzled for ldmatrix (128B rows, 8 16B units).
// swizzle: 16B-unit u -> u ^ (row&7)
// ---------------------------------------------------------------------------
__global__ void prep_bsplit(const float* __restrict__ e0, const float* __restrict__ e1,
                            const float* __restrict__ e2, const int* __restrict__ idxp) {
    int idxv = *idxp;
    int K = (idxv == 0) ? 512 : 1024;
    int k = blockIdx.x;
    if (k >= K) return;
    int d = threadIdx.x;                       // 0..63
    float v = code_row(k, e0, e1, e2, idxv)[d];
    __nv_bfloat16 hb = __float2bfloat16_rn(v);
    unsigned char* buf = g_bsplit + (size_t)(k >> 8) * 32768;
    int r = k & 255;
    int u = d >> 3;
    int inb = (2 * d) & 15;
    *(__nv_bfloat16*)(buf + r * 128 + (((u) ^ (r & 7)) << 4) + inb) = hb;
}

// ---------------------------------------------------------------------------
// Kernel 2: HMMA scoring (single-term xh.c; fp32 norms added in epilogue)
// + per-lane TOP-3 (recall fix for R14's 1-3 candidate misses)
// + two-tier rescue (fp32 re-rank, fp64 tiebreak) + output/loss/hist.
// 16 MMAs per n-group.
// ---------------------------------------------------------------------------
__global__ __launch_bounds__(TPB, 2)
void vq_hmma(const float* __restrict__ X,
             const float* __restrict__ e0, const float* __restrict__ e1,
             const float* __restrict__ e2, const int* __restrict__ idxp,
             float* __restrict__ out) {
    extern __shared__ __align__(1024) char smem[];
    const uint32_t sb = smem_u32(smem);
    const int tid = threadIdx.x;
    const int warp = tid >> 5, lane = tid & 31;
    const int q = lane & 3, lr = lane & 7, grp = lane >> 3;
    const int idxv = *idxp;
    const int K = (idxv == 0) ? 512 : 1024;
    const int nch = K >> 8;
    const int pbase = blockIdx.x * CTA_PIX;

    // ---- stage A tile (xh only, 128B rows) swizzled + fp32 norms ----
    {
        int r = tid;
        int p = pbase + r;
        int b = p >> 12;
        size_t xb = (size_t)b * (D * HW) + (p & (HW - 1));
        #pragma unroll
        for (int j = 0; j < 32; j++) {
            float v0 = X[xb + (size_t)(2 * j) * HW];
            float v1 = X[xb + (size_t)(2 * j + 1) * HW];
            __nv_bfloat16 h0 = __float2bfloat16_rn(v0), h1 = __float2bfloat16_rn(v1);
            uint32_t hp = (uint32_t)__bfloat16_as_ushort(h0)
                        | ((uint32_t)__bfloat16_as_ushort(h1) << 16);
            int u = j >> 2;                 // byte col 4j -> 16B unit (0..7)
            int inb = (4 * j) & 15;
            *(uint32_t*)(smem + SM_A + r * 128 + (((u) ^ (r & 7)) << 4) + inb) = hp;
        }
        float* shn = (float*)(smem + SM_SHN);
        for (int i = tid; i < KMAX; i += TPB) shn[i] = g_shn[i];
    }
    __syncthreads();

    // ---- persistent A fragments: xh [mtile][ktile][4 regs] ----
    uint32_t xh[2][4][4];
    #pragma unroll
    for (int mt = 0; mt < 2; mt++)
        #pragma unroll
        for (int kt = 0; kt < 4; kt++) {
            int row = warp * 32 + mt * 16 + ((grp & 1) << 3) + lr;
            int uh = kt * 2 + (grp >> 1);
            LDSM_X4(xh[mt][kt][0], xh[mt][kt][1], xh[mt][kt][2], xh[mt][kt][3],
                    sb + SM_A + row * 128 + (((uh) ^ lr) << 4));
        }
    __syncthreads();   // A region dead: B chunks may now overwrite it

    // per-lane TOP-3 per pixel-slot over this lane's 256-code subset
    float s1[4], s2[4], s3[4];
    int i1[4], i2[4], i3[4];
    #pragma unroll
    for (int sl = 0; sl < 4; sl++) {
        s1[sl] = -3.4e38f; s2[sl] = -3.4e38f; s3[sl] = -3.4e38f;
        i1[sl] = 0; i2[sl] = 0; i3[sl] = 0;
    }

    const float2* shnf = (const float2*)(smem + SM_SHN);

    for (int ch = 0; ch < nch; ch++) {
        // stage B chunk (32 KB, swizzle preserved by raw copy) over dead A
        {
            const uint4* src = (const uint4*)(g_bsplit + (size_t)ch * 32768);
            uint4* dst = (uint4*)(smem + SM_B);
            #pragma unroll
            for (int i = 0; i < 8; i++) dst[tid + i * TPB] = src[tid + i * TPB];
        }
        __syncthreads();
        const int kb = ch << 8;

        #pragma unroll 1
        for (int ng = 0; ng < 16; ng++) {
            const int nt0 = ng * 2;
            float dx[2][2][4];                       // [mtile][ntile][reg]
            #pragma unroll
            for (int a = 0; a < 2; a++)
                #pragma unroll
                for (int bb = 0; bb < 2; bb++)
                    #pragma unroll
                    for (int c = 0; c < 4; c++) dx[a][bb][c] = 0.f;

            #pragma unroll
            for (int p2 = 0; p2 < 2; p2++) {       // ktile pairs
                uint32_t b0[4], b1[4];
                {
                    int u = p2 * 4 + grp;
                    int row0 = nt0 * 8 + lr;
                    LDSM_X4(b0[0], b0[1], b0[2], b0[3],
                            sb + SM_B + row0 * 128 + (((u) ^ lr) << 4));
                    int row1 = (nt0 + 1) * 8 + lr;
                    LDSM_X4(b1[0], b1[1], b1[2], b1[3],
                            sb + SM_B + row1 * 128 + (((u) ^ lr) << 4));
                }
                #pragma unroll
                for (int k2 = 0; k2 < 2; k2++) {
                    const int kt = p2 * 2 + k2;
                    MMA(dx[0][0], xh[0][kt][0], xh[0][kt][1], xh[0][kt][2], xh[0][kt][3], b0[k2*2], b0[k2*2+1]);
                    MMA(dx[0][1], xh[0][kt][0], xh[0][kt][1], xh[0][kt][2], xh[0][kt][3], b1[k2*2], b1[k2*2+1]);
                    MMA(dx[1][0], xh[1][kt][0], xh[1][kt][1], xh[1][kt][2], xh[1][kt][3], b0[k2*2], b0[k2*2+1]);
                    MMA(dx[1][1], xh[1][kt][0], xh[1][kt][1], xh[1][kt][2], xh[1][kt][3], b1[k2*2], b1[k2*2+1]);
                }
            }

            // epilogue: add fp32 norm (index includes kb!), top-3 insert.
            // D frag: d0,d1 = (row lane/4, cols n,n+1); d2,d3 = (+8 rows);
            // n = kb + ntile*8 + 2q
            float2 nA = shnf[(kb + nt0 * 8 + q * 2) >> 1];
            float2 nB = shnf[(kb + (nt0 + 1) * 8 + q * 2) >> 1];
            #pragma unroll
            for (int mt = 0; mt < 2; mt++)
                #pragma unroll
                for (int j = 0; j < 2; j++) {
                    const int nb = kb + (nt0 + j) * 8 + q * 2;
                    const float2 nn = j ? nB : nA;
                    #pragma unroll
                    for (int e = 0; e < 4; e++) {
                        const int sl = mt * 2 + (e >> 1);
                        const int kk = nb + (e & 1);
                        float v = dx[mt][j][e] + ((e & 1) ? nn.y : nn.x);
                        if (v > s3[sl]) {
                            if (v > s2[sl]) {
                                if (v > s1[sl]) {
                                    s3[sl] = s2[sl]; i3[sl] = i2[sl];
                                    s2[sl] = s1[sl]; i2[sl] = i1[sl];
                                    s1[sl] = v; i1[sl] = kk;
                                } else {
                                    s3[sl] = s2[sl]; i3[sl] = i2[sl];
                                    s2[sl] = v; i2[sl] = kk;
                                }
                            } else { s3[sl] = v; i3[sl] = kk; }
                        }
                    }
                }
        }
        __syncthreads();   // all reads of this B buffer done before reuse
    }

    // ---- publish 12 candidates per pixel (4 quad lanes x top-3) ----
    {
        float* CS = (float*)(smem + SM_CS);
        int*   CI = (int*)(smem + SM_CI);
        #pragma unroll
        for (int sl = 0; sl < 4; sl++) {
            int pl = warp * 32 + (sl >> 1) * 16 + (sl & 1) * 8 + (lane >> 2);
            CS[pl * 12 + q * 3 + 0] = s1[sl];
            CS[pl * 12 + q * 3 + 1] = s2[sl];
            CS[pl * 12 + q * 3 + 2] = s3[sl];
            CI[pl * 12 + q * 3 + 0] = i1[sl];
            CI[pl * 12 + q * 3 + 1] = i2[sl];
            CI[pl * 12 + q * 3 + 2] = i3[sl];
        }
    }
    __syncthreads();

    // ---- phase 2: merge 12 candidates, two-tier rescue, output/loss ----
    {
        const int p = pbase + tid;
        const int b = p >> 12;
        const size_t xb = (size_t)b * (D * HW) + (p & (HW - 1));
        float cs[12]; int ci[12];
        {
            const float* CS = (const float*)(smem + SM_CS);
            const int*   CI = (const int*)(smem + SM_CI);
            #pragma unroll
            for (int m = 0; m < 12; m++) { cs[m] = CS[tid * 12 + m]; ci[m] = CI[tid * 12 + m]; }
        }
        float fs1 = -3.4e38f, fs2 = -3.4e38f; int w1 = 0;
        #pragma unroll
        for (int m = 0; m < 12; m++) {
            if (cs[m] > fs1) { fs2 = fs1; fs1 = cs[m]; w1 = ci[m]; }
            else if (cs[m] > fs2) fs2 = cs[m];
        }

        if (fs1 - fs2 < MARGIN_T) {
            // Tier 1: fp32 exact-distance re-rank of in-window candidates,
            // 4-way ILP. Track top-2 exact distances.
            float b1 = 3.4e38f, b2 = 3.4e38f;
            int bi1 = 0x7fffffff, bi2 = 0x7fffffff;
            const float thr = fs1 - MARGIN_T;
            for (int m = 0; m < 12; m++) {
                if (cs[m] > thr) {
                    const float* c = code_row(ci[m], e0, e1, e2, idxv);
                    float a0 = 0.f, a1 = 0.f, a2 = 0.f, a3 = 0.f;
                    #pragma unroll
                    for (int d = 0; d < D; d += 4) {
                        float t0 = X[xb + (size_t)(d    ) * HW] - c[d];
                        float t1 = X[xb + (size_t)(d + 1) * HW] - c[d + 1];
                        float t2 = X[xb + (size_t)(d + 2) * HW] - c[d + 2];
                        float t3 = X[xb + (size_t)(d + 3) * HW] - c[d + 3];
                        a0 += t0 * t0; a1 += t1 * t1;
                        a2 += t2 * t2; a3 += t3 * t3;
                    }
                    float dd = (a0 + a1) + (a2 + a3);
                    int cidx = ci[m];
                    if (dd < b1 || (dd == b1 && cidx < bi1)) {
                        b2 = b1; bi2 = bi1; b1 = dd; bi1 = cidx;
                    } else if (dd < b2 || (dd == b2 && cidx < bi2)) {
                        b2 = dd; bi2 = cidx;
                    }
                }
            }
            w1 = bi1;
            // Tier 2: fp64 tiebreak of the fp32 top-2 only (rare)
            if (b2 - b1 < 1e-3f && bi2 != 0x7fffffff) {
                const float* c1 = code_row(bi1, e0, e1, e2, idxv);
                const float* c2 = code_row(bi2, e0, e1, e2, idxv);
                double d1 = 0.0, d2 = 0.0;
                for (int d = 0; d < D; d++) {
                    double xv = (double)X[xb + (size_t)d * HW];
                    double t1 = xv - (double)c1[d]; d1 += t1 * t1;
                    double t2 = xv - (double)c2[d]; d2 += t2 * t2;
                }
                if (d2 < d1 || (d2 == d1 && bi2 < bi1)) w1 = bi2;
            }
        }
        atomicAdd(&g_hist[w1], 1);

        const float* cw = code_row(w1, e0, e1, e2, idxv);
        float lsum = 0.f;
        #pragma unroll 8
        for (int d = 0; d < D; d++) {
            float xv = X[xb + (size_t)d * HW];
            float df = cw[d] - xv;
            out[xb + (size_t)d * HW] = xv + df;   // STE, reference rounding
            lsum += df * df;
        }
        float* red = (float*)(smem + SM_RED);
        red[tid] = lsum;
        __syncthreads();
        for (int off = TPB / 2; off > 0; off >>= 1) {
            if (tid < off) red[tid] += red[tid + off];
            __syncthreads();
        }
        if (tid == 0) atomicAdd(&g_lossacc, red[0]);
    }
}

// ---------------------------------------------------------------------------
// Kernel 3: finalize loss + perplexity
// ---------------------------------------------------------------------------
__global__ void finalize_kernel(const int* __restrict__ idxp, float* __restrict__ out,
                                int out_size) {
    __shared__ float red[1024];
    int t = threadIdx.x;
    int idxv = *idxp;
    int K = (idxv == 0) ? 512 : 1024;
    float v = 0.f;
    if (t < K) {
        float pr = (float)g_hist[t] * (1.0f / (float)NPIX);
        v = pr * logf(pr + 1e-10f);
    }
    red[t] = v;
    __syncthreads();
    for (int off = 512; off > 0; off >>= 1) {
        if (t < off) red[t] += red[t + off];
        __syncthreads();
    }
    if (t == 0) {
        float mse = g_lossacc / (float)OUT_ELEMS;
        out[OUT_ELEMS]     = mse + 0.25f * mse;   // q_latent + 0.25*e_latent
        out[OUT_ELEMS + 1] = expf(-red[0]);       // perplexity
    }
    for (int i = OUT_ELEMS + 2 + t; i < out_size; i += 1024) out[i] = 0.f;
}

// ---------------------------------------------------------------------------
extern "C" void kernel_launch(void* const* d_in, const int* in_sizes, int n_in,
                              void* d_out, int out_size) {
    const float* x  = (const float*)d_in[0];
    const float* e0 = (const float*)d_in[1];
    const float* e1 = (const float*)d_in[2];
    const float* e2 = (const float*)d_in[3];
    const int*   ip = (const int*)d_in[4];
    float* out = (float*)d_out;

    cudaFuncSetAttribute(vq_hmma, cudaFuncAttributeMaxDynamicSharedMemorySize,
                         SMEM_TOTAL);

    prep_norms<<<256, 128>>>(e0, e1, e2, ip);
    prep_bsplit<<<KMAX, 64>>>(e0, e1, e2, ip);
    vq_hmma<<<NPIX / CTA_PIX, TPB, SMEM_TOTAL>>>(x, e0, e1, e2, ip, out);
    finalize_kernel<<<1, 1024>>>(ip, out, out_size);
}

// round 17
// speedup vs baseline: 1.1942x; 1.1942x over previous
#include <cuda_runtime.h>
#include <cuda_bf16.h>
#include <cstdint>

// Problem: x [32,64,64,64] NCHW fp32, emb0/1/2 [512,64] fp32, idx int
#define NPIX   131072
#define D      64
#define HW     4096
#define KMAX   1024
#define OUT_ELEMS 8388608
#define CTA_PIX 256
#define TPB    256
#define MARGIN_T 0.18f

// smem layout (bytes). B0/B1 (32 KB each, double-buffered) overlay dead A
// (64 KB staging region). Total 70 KB -> 2 CTAs/SM.
#define SM_A    0            // 256 rows x 256B (xh|xl bf16, swizzled) = 64 KB
#define SM_B0   0            // 256 rows x 128B (c bf16, swizzled) overlay
#define SM_B1   32768        // second buffer overlay
#define SM_SHN2 65536        // 1024 u32 packed (-norm hi, -norm lo) = 4 KB
#define SMEM_TOTAL 70656
// phase-2 overlays (inside dead A/B region, after final chunk syncthreads)
#define SM_CS   0            // 256 x 8 f32 candidate scores (8 KB)
#define SM_CI   8192         // 256 x 8 i32 candidate indices (8 KB)
#define SM_RED  16384        // 256 f32

// Scratch (no cudaMalloc allowed)
__device__ int      g_hist[KMAX];
__device__ uint32_t g_shn2[KMAX];
__device__ float    g_lossacc;
// bf16 codes, swizzled per-256-row chunk: 4 chunks x 256 rows x 128B
__device__ __align__(16) unsigned char g_bsplit[KMAX * 128];

// ---------------------------------------------------------------------------
__device__ __forceinline__ uint32_t smem_u32(const void* p) {
    uint32_t a;
    asm("{ .reg .u64 t; cvta.to.shared.u64 t, %1; cvt.u32.u64 %0, t; }"
        : "=r"(a) : "l"(p));
    return a;
}

#define LDSM_X4(r0, r1, r2, r3, addr) \
    asm volatile("ldmatrix.sync.aligned.m8n8.x4.shared.b16 {%0,%1,%2,%3}, [%4];" \
        : "=r"(r0), "=r"(r1), "=r"(r2), "=r"(r3) : "r"(addr))

#define MMA(dd, a0, a1, a2, a3, b0, b1) \
    asm volatile("mma.sync.aligned.m16n8k16.row.col.f32.bf16.bf16.f32 " \
        "{%0,%1,%2,%3},{%4,%5,%6,%7},{%8,%9},{%0,%1,%2,%3};" \
        : "+f"((dd)[0]), "+f"((dd)[1]), "+f"((dd)[2]), "+f"((dd)[3]) \
        : "r"(a0), "r"(a1), "r"(a2), "r"(a3), "r"(b0), "r"(b1))

#define CP_ASYNC16(dst, src) \
    asm volatile("cp.async.cg.shared.global [%0], [%1], 16;" :: "r"(dst), "l"(src))
#define CP_COMMIT() asm volatile("cp.async.commit_group;" ::: "memory")
#define CP_WAIT0()  asm volatile("cp.async.wait_group 0;" ::: "memory")
#define CP_WAIT1()  asm volatile("cp.async.wait_group 1;" ::: "memory")

__device__ __forceinline__ const float* code_row(int k, const float* e0,
                                                 const float* e1, const float* e2,
                                                 int idxv) {
    if (k < 512) return e0 + (size_t)k * D;
    const float* e = (idxv == 1) ? e1 : e2;
    return e + (size_t)(k - 512) * D;
}

// ---------------------------------------------------------------------------
// Kernel 0: zero hist/loss + packed bf16-split of (-0.5*||c||^2) per code
// ---------------------------------------------------------------------------
__global__ void prep_norms(const float* __restrict__ e0, const float* __restrict__ e1,
                           const float* __restrict__ e2, const int* __restrict__ idxp) {
    int idxv = *idxp;
    int K = (idxv == 0) ? 512 : 1024;
    int lane = threadIdx.x & 31;
    int k = blockIdx.x * 4 + (threadIdx.x >> 5);
    float s = 0.f;
    if (k < K) {
        const float* c = code_row(k, e0, e1, e2, idxv);
        float a = c[lane], b = c[lane + 32];
        s = a * a + b * b;
    }
    #pragma unroll
    for (int off = 16; off > 0; off >>= 1) s += __shfl_xor_sync(0xffffffffu, s, off);
    if (lane == 0) {
        float neg = -0.5f * s;
        __nv_bfloat16 nh = __float2bfloat16_rn(neg);
        __nv_bfloat16 nl = __float2bfloat16_rn(neg - __bfloat162float(nh));
        g_shn2[k] = (uint32_t)__bfloat16_as_ushort(nh)
                  | ((uint32_t)__bfloat16_as_ushort(nl) << 16);
        g_hist[k] = 0;
        if (k == 0) g_lossacc = 0.f;
    }
}

// ---------------------------------------------------------------------------
// Kernel 1: codes -> bf16 (plain), swizzled for ldmatrix (128B rows).
// swizzle: 16B-unit u -> u ^ (row&7)
// ---------------------------------------------------------------------------
__global__ void prep_bsplit(const float* __restrict__ e0, const float* __restrict__ e1,
                            const float* __restrict__ e2, const int* __restrict__ idxp) {
    int idxv = *idxp;
    int K = (idxv == 0) ? 512 : 1024;
    int k = blockIdx.x;
    if (k >= K) return;
    int d = threadIdx.x;                       // 0..63
    float v = code_row(k, e0, e1, e2, idxv)[d];
    __nv_bfloat16 hb = __float2bfloat16_rn(v);
    unsigned char* buf = g_bsplit + (size_t)(k >> 8) * 32768;
    int r = k & 255;
    int u = d >> 3;
    int inb = (2 * d) & 15;
    *(__nv_bfloat16*)(buf + r * 128 + (((u) ^ (r & 7)) << 4) + inb) = hb;
}

// ---------------------------------------------------------------------------
// Kernel 2: HMMA scoring (2-term x-split: xh.c + xl.c, + norm k-tile MMA)
// + cheap per-lane top-2 + two-tier rescue (fp32 re-rank, fp64 tiebreak)
// + output/loss/hist. B chunks double-buffered via cp.async over dead A.
// Scoring numerics are BIT-IDENTICAL to the R12 kernel (168us, exact).
// ---------------------------------------------------------------------------
__global__ __launch_bounds__(TPB, 2)
void vq_hmma(const float* __restrict__ X,
             const float* __restrict__ e0, const float* __restrict__ e1,
             const float* __restrict__ e2, const int* __restrict__ idxp,
             float* __restrict__ out) {
    extern __shared__ __align__(1024) char smem[];
    const uint32_t sb = smem_u32(smem);
    const int tid = threadIdx.x;
    const int warp = tid >> 5, lane = tid & 31;
    const int q = lane & 3, lr = lane & 7, grp = lane >> 3;
    const int idxv = *idxp;
    const int K = (idxv == 0) ? 512 : 1024;
    const int nch = K >> 8;
    const int pbase = blockIdx.x * CTA_PIX;

    // ---- stage A tile (xh|xl, 256B rows) swizzled + shn2 ----
    {
        int r = tid;
        int p = pbase + r;
        int b = p >> 12;
        size_t xb = (size_t)b * (D * HW) + (p & (HW - 1));
        #pragma unroll
        for (int j = 0; j < 32; j++) {
            float v0 = X[xb + (size_t)(2 * j) * HW];
            float v1 = X[xb + (size_t)(2 * j + 1) * HW];
            __nv_bfloat16 h0 = __float2bfloat16_rn(v0), h1 = __float2bfloat16_rn(v1);
            __nv_bfloat16 l0 = __float2bfloat16_rn(v0 - __bfloat162float(h0));
            __nv_bfloat16 l1 = __float2bfloat16_rn(v1 - __bfloat162float(h1));
            uint32_t hp = (uint32_t)__bfloat16_as_ushort(h0)
                        | ((uint32_t)__bfloat16_as_ushort(h1) << 16);
            uint32_t lp = (uint32_t)__bfloat16_as_ushort(l0)
                        | ((uint32_t)__bfloat16_as_ushort(l1) << 16);
            int u = j >> 2;
            int inb = (4 * j) & 15;
            *(uint32_t*)(smem + SM_A + r * 256 + (((u)     ^ (r & 7)) << 4) + inb) = hp;
            *(uint32_t*)(smem + SM_A + r * 256 + (((u + 8) ^ (r & 7)) << 4) + inb) = lp;
        }
        uint32_t* sh2 = (uint32_t*)(smem + SM_SHN2);
        for (int i = tid; i < KMAX; i += TPB) sh2[i] = g_shn2[i];
    }
    __syncthreads();

    // ---- persistent A fragments: xh/xl [mtile][ktile][4 regs] ----
    uint32_t xh[2][4][4], xl[2][4][4];
    #pragma unroll
    for (int mt = 0; mt < 2; mt++)
        #pragma unroll
        for (int kt = 0; kt < 4; kt++) {
            int row = warp * 32 + mt * 16 + ((grp & 1) << 3) + lr;
            int uh = kt * 2 + (grp >> 1);
            LDSM_X4(xh[mt][kt][0], xh[mt][kt][1], xh[mt][kt][2], xh[mt][kt][3],
                    sb + SM_A + row * 256 + (((uh) ^ lr) << 4));
            int ul = 8 + kt * 2 + (grp >> 1);
            LDSM_X4(xl[mt][kt][0], xl[mt][kt][1], xl[mt][kt][2], xl[mt][kt][3],
                    sb + SM_A + row * 256 + (((ul) ^ lr) << 4));
        }
    __syncthreads();   // A region dead: B buffers may now overwrite it

    // prefetch B chunk 0 into B0 (cp.async, raw copy preserves swizzle)
    {
        const char* src = (const char*)g_bsplit + tid * 16;
        uint32_t dst = sb + SM_B0 + tid * 16;
        #pragma unroll
        for (int i = 0; i < 8; i++)
            CP_ASYNC16(dst + i * TPB * 16, src + (size_t)i * TPB * 16);
        CP_COMMIT();
    }

    // per-lane top-2 per pixel-slot over this lane's 256-code subset
    float s1[4], s2[4];
    int i1[4], i2[4];
    #pragma unroll
    for (int sl = 0; sl < 4; sl++) { s1[sl] = -3.4e38f; s2[sl] = -3.4e38f; i1[sl] = 0; i2[sl] = 0; }

    const uint32_t aext = (q == 0) ? 0x3F803F80u : 0u;   // (1.0,1.0) bf16
    const uint32_t* sh2 = (const uint32_t*)(smem + SM_SHN2);

    for (int ch = 0; ch < nch; ch++) {
        // prefetch next chunk into the other buffer, then wait for current
        if (ch + 1 < nch) {
            const char* src = (const char*)g_bsplit + (size_t)(ch + 1) * 32768 + tid * 16;
            uint32_t dst = sb + (((ch + 1) & 1) ? SM_B1 : SM_B0) + tid * 16;
            #pragma unroll
            for (int i = 0; i < 8; i++)
                CP_ASYNC16(dst + i * TPB * 16, src + (size_t)i * TPB * 16);
            CP_COMMIT();
            CP_WAIT1();          // current chunk's group complete
        } else {
            CP_WAIT0();
        }
        __syncthreads();
        const uint32_t bB = sb + ((ch & 1) ? SM_B1 : SM_B0);
        const int kb = ch << 8;

        #pragma unroll 1
        for (int ng = 0; ng < 16; ng++) {
            const int nt0 = ng * 2;
            float dx[2][2][4];                       // [mtile][ntile][reg]
            #pragma unroll
            for (int a = 0; a < 2; a++)
                #pragma unroll
                for (int bb = 0; bb < 2; bb++)
                    #pragma unroll
                    for (int c = 0; c < 4; c++) dx[a][bb][c] = 0.f;

            // norm k-tile: ones-column (k0,k1) x (-norm hi, -norm lo).
            // a0 = rows lane/4 @ k0-1, a1 = rows lane/4+8 @ k0-1 (both need ones)
            uint32_t be0 = 0, be1 = 0;
            if (q == 0) {
                be0 = sh2[kb + nt0 * 8 + (lane >> 2)];
                be1 = sh2[kb + nt0 * 8 + 8 + (lane >> 2)];
            }
            MMA(dx[0][0], aext, aext, 0u, 0u, be0, 0u);
            MMA(dx[0][1], aext, aext, 0u, 0u, be1, 0u);
            MMA(dx[1][0], aext, aext, 0u, 0u, be0, 0u);
            MMA(dx[1][1], aext, aext, 0u, 0u, be1, 0u);

            #pragma unroll
            for (int p2 = 0; p2 < 2; p2++) {       // ktile pairs, B shared by xh/xl
                uint32_t b0[4], b1[4];
                {
                    int u = p2 * 4 + grp;
                    int row0 = nt0 * 8 + lr;
                    LDSM_X4(b0[0], b0[1], b0[2], b0[3],
                            bB + row0 * 128 + (((u) ^ lr) << 4));
                    int row1 = (nt0 + 1) * 8 + lr;
                    LDSM_X4(b1[0], b1[1], b1[2], b1[3],
                            bB + row1 * 128 + (((u) ^ lr) << 4));
                }
                #pragma unroll
                for (int k2 = 0; k2 < 2; k2++) {
                    const int kt = p2 * 2 + k2;
                    MMA(dx[0][0], xh[0][kt][0], xh[0][kt][1], xh[0][kt][2], xh[0][kt][3], b0[k2*2], b0[k2*2+1]);
                    MMA(dx[0][1], xh[0][kt][0], xh[0][kt][1], xh[0][kt][2], xh[0][kt][3], b1[k2*2], b1[k2*2+1]);
                    MMA(dx[1][0], xh[1][kt][0], xh[1][kt][1], xh[1][kt][2], xh[1][kt][3], b0[k2*2], b0[k2*2+1]);
                    MMA(dx[1][1], xh[1][kt][0], xh[1][kt][1], xh[1][kt][2], xh[1][kt][3], b1[k2*2], b1[k2*2+1]);
                    MMA(dx[0][0], xl[0][kt][0], xl[0][kt][1], xl[0][kt][2], xl[0][kt][3], b0[k2*2], b0[k2*2+1]);
                    MMA(dx[0][1], xl[0][kt][0], xl[0][kt][1], xl[0][kt][2], xl[0][kt][3], b1[k2*2], b1[k2*2+1]);
                    MMA(dx[1][0], xl[1][kt][0], xl[1][kt][1], xl[1][kt][2], xl[1][kt][3], b0[k2*2], b0[k2*2+1]);
                    MMA(dx[1][1], xl[1][kt][0], xl[1][kt][1], xl[1][kt][2], xl[1][kt][3], b1[k2*2], b1[k2*2+1]);
                }
            }

            // cheap top-2 insert (R5/R10/R12-proven). D frag: d0,d1 = (row
            // lane/4, cols n,n+1); d2,d3 = (+8 rows); n = kb + ntile*8 + 2q
            #pragma unroll
            for (int mt = 0; mt < 2; mt++)
                #pragma unroll
                for (int j = 0; j < 2; j++) {
                    const int nb = kb + (nt0 + j) * 8 + q * 2;
                    #pragma unroll
                    for (int e = 0; e < 4; e++) {
                        const int sl = mt * 2 + (e >> 1);
                        const int kk = nb + (e & 1);
                        float v = dx[mt][j][e];
                        if (v > s2[sl]) {
                            if (v > s1[sl]) { s2[sl] = s1[sl]; i2[sl] = i1[sl]; s1[sl] = v; i1[sl] = kk; }
                            else            { s2[sl] = v; i2[sl] = kk; }
                        }
                    }
                }
        }
        __syncthreads();   // all reads of this B buffer done before its reuse
    }

    // ---- publish 8 candidates per pixel (4 quad lanes x top-2) ----
    {
        float* CS = (float*)(smem + SM_CS);
        int*   CI = (int*)(smem + SM_CI);
        #pragma unroll
        for (int sl = 0; sl < 4; sl++) {
            int pl = warp * 32 + (sl >> 1) * 16 + (sl & 1) * 8 + (lane >> 2);
            CS[pl * 8 + q * 2 + 0] = s1[sl];
            CS[pl * 8 + q * 2 + 1] = s2[sl];
            CI[pl * 8 + q * 2 + 0] = i1[sl];
            CI[pl * 8 + q * 2 + 1] = i2[sl];
        }
    }
    __syncthreads();

    // ---- phase 2: merge 8 candidates, two-tier rescue, output/loss ----
    {
        const int p = pbase + tid;
        const int b = p >> 12;
        const size_t xb = (size_t)b * (D * HW) + (p & (HW - 1));
        float cs[8]; int ci[8];
        {
            const float* CS = (const float*)(smem + SM_CS);
            const int*   CI = (const int*)(smem + SM_CI);
            #pragma unroll
            for (int m = 0; m < 8; m++) { cs[m] = CS[tid * 8 + m]; ci[m] = CI[tid * 8 + m]; }
        }
        float fs1 = -3.4e38f, fs2 = -3.4e38f; int w1 = 0;
        #pragma unroll
        for (int m = 0; m < 8; m++) {
            if (cs[m] > fs1) { fs2 = fs1; fs1 = cs[m]; w1 = ci[m]; }
            else if (cs[m] > fs2) fs2 = cs[m];
        }

        if (fs1 - fs2 < MARGIN_T) {
            // Tier 1: fp32 exact-distance re-rank of in-window candidates,
            // 4-way ILP, float4 code loads. Track top-2 exact distances.
            float b1 = 3.4e38f, b2 = 3.4e38f;
            int bi1 = 0x7fffffff, bi2 = 0x7fffffff;
            const float thr = fs1 - MARGIN_T;
            for (int m = 0; m < 8; m++) {
                if (cs[m] > thr) {
                    const float4* c4 = (const float4*)code_row(ci[m], e0, e1, e2, idxv);
                    float a0 = 0.f, a1 = 0.f, a2 = 0.f, a3 = 0.f;
                    #pragma unroll
                    for (int d = 0; d < D; d += 4) {
                        float4 cv = c4[d >> 2];
                        float t0 = X[xb + (size_t)(d    ) * HW] - cv.x;
                        float t1 = X[xb + (size_t)(d + 1) * HW] - cv.y;
                        float t2 = X[xb + (size_t)(d + 2) * HW] - cv.z;
                        float t3 = X[xb + (size_t)(d + 3) * HW] - cv.w;
                        a0 += t0 * t0; a1 += t1 * t1;
                        a2 += t2 * t2; a3 += t3 * t3;
                    }
                    float dd = (a0 + a1) + (a2 + a3);
                    int cidx = ci[m];
                    if (dd < b1 || (dd == b1 && cidx < bi1)) {
                        b2 = b1; bi2 = bi1; b1 = dd; bi1 = cidx;
                    } else if (dd < b2 || (dd == b2 && cidx < bi2)) {
                        b2 = dd; bi2 = cidx;
                    }
                }
            }
            w1 = bi1;
            // Tier 2: fp64 tiebreak of the fp32 top-2 only (rare)
            if (b2 - b1 < 1e-3f && bi2 != 0x7fffffff) {
                const float* c1 = code_row(bi1, e0, e1, e2, idxv);
                const float* c2 = code_row(bi2, e0, e1, e2, idxv);
                double d1 = 0.0, d2 = 0.0;
                for (int d = 0; d < D; d++) {
                    double xv = (double)X[xb + (size_t)d * HW];
                    double t1 = xv - (double)c1[d]; d1 += t1 * t1;
                    double t2 = xv - (double)c2[d]; d2 += t2 * t2;
                }
                if (d2 < d1 || (d2 == d1 && bi2 < bi1)) w1 = bi2;
            }
        }
        atomicAdd(&g_hist[w1], 1);

        // Gather winner via float4 (code rows are 256B contiguous)
        const float4* cw4 = (const float4*)code_row(w1, e0, e1, e2, idxv);
        float lsum = 0.f;
        #pragma unroll
        for (int d4 = 0; d4 < D / 4; d4++) {
            float4 cv = cw4[d4];
            int d = d4 * 4;
            float x0 = X[xb + (size_t)(d    ) * HW];
            float x1 = X[xb + (size_t)(d + 1) * HW];
            float x2 = X[xb + (size_t)(d + 2) * HW];
            float x3 = X[xb + (size_t)(d + 3) * HW];
            float f0 = cv.x - x0, f1 = cv.y - x1, f2 = cv.z - x2, f3 = cv.w - x3;
            out[xb + (size_t)(d    ) * HW] = x0 + f0;   // STE, reference rounding
            out[xb + (size_t)(d + 1) * HW] = x1 + f1;
            out[xb + (size_t)(d + 2) * HW] = x2 + f2;
            out[xb + (size_t)(d + 3) * HW] = x3 + f3;
            lsum += f0 * f0 + f1 * f1 + f2 * f2 + f3 * f3;
        }
        float* red = (float*)(smem + SM_RED);
        red[tid] = lsum;
        __syncthreads();
        for (int off = TPB / 2; off > 0; off >>= 1) {
            if (tid < off) red[tid] += red[tid + off];
            __syncthreads();
        }
        if (tid == 0) atomicAdd(&g_lossacc, red[0]);
    }
}

// ---------------------------------------------------------------------------
// Kernel 3: finalize loss + perplexity
// ---------------------------------------------------------------------------
__global__ void finalize_kernel(const int* __restrict__ idxp, float* __restrict__ out,
                                int out_size) {
    __shared__ float red[1024];
    int t = threadIdx.x;
    int idxv = *idxp;
    int K = (idxv == 0) ? 512 : 1024;
    float v = 0.f;
    if (t < K) {
        float pr = (float)g_hist[t] * (1.0f / (float)NPIX);
        v = pr * logf(pr + 1e-10f);
    }
    red[t] = v;
    __syncthreads();
    for (int off = 512; off > 0; off >>= 1) {
        if (t < off) red[t] += red[t + off];
        __syncthreads();
    }
    if (t == 0) {
        float mse = g_lossacc / (float)OUT_ELEMS;
        out[OUT_ELEMS]     = mse + 0.25f * mse;   // q_latent + 0.25*e_latent
        out[OUT_ELEMS + 1] = expf(-red[0]);       // perplexity
    }
    for (int i = OUT_ELEMS + 2 + t; i < out_size; i += 1024) out[i] = 0.f;
}

// ---------------------------------------------------------------------------
extern "C" void kernel_launch(void* const* d_in, const int* in_sizes, int n_in,
                              void* d_out, int out_size) {
    const float* x  = (const float*)d_in[0];
    const float* e0 = (const float*)d_in[1];
    const float* e1 = (const float*)d_in[2];
    const float* e2 = (const float*)d_in[3];
    const int*   ip = (const int*)d_in[4];
    float* out = (float*)d_out;

    cudaFuncSetAttribute(vq_hmma, cudaFuncAttributeMaxDynamicSharedMemorySize,
                         SMEM_TOTAL);

    prep_norms<<<256, 128>>>(e0, e1, e2, ip);
    prep_bsplit<<<KMAX, 64>>>(e0, e1, e2, ip);
    vq_hmma<<<NPIX / CTA_PIX, TPB, SMEM_TOTAL>>>(x, e0, e1, e2, ip, out);
    finalize_kernel<<<1, 1024>>>(ip, out, out_size);
}